// round 12
// baseline (speedup 1.0000x reference)
#include <cuda_runtime.h>
#include <math_constants.h>

#define BD   64
#define MAXB 8192
#define MAXM 16384
#define TS   132   // smem row stride (floats) for transposed tiles

// ---------------- device scratch (static: no allocations allowed) ----------
__device__ float g_an[MAXB * BD];                    // normalized anchors
__device__ float g_cn[MAXM * BD];                    // normalized candidates (pos ++ neg)
__device__ float g_logits[(size_t)MAXB * MAXM];      // full sim matrix (512 MB)
__device__ float g_diag[MAXB];                       // diagonal (bit-identical to GEMM chain)
__device__ int   g_thresh[MAXB];                     // per-row threshold, ordered-int encoding
__device__ float g_topv[MAXB * 32];
__device__ int   g_topi[MAXB * 32];

// ordered-int encoding: monotone map float -> int so atomicMin works on floats
__device__ __forceinline__ int fkey(float f) {
    int i = __float_as_int(f);
    return i >= 0 ? i : (i ^ 0x7FFFFFFF);
}
__device__ __forceinline__ float funkey(int k) {
    return __int_as_float(k >= 0 ? k : (k ^ 0x7FFFFFFF));
}

#define FMA_F32X2(d, a, b, c) \
    asm("fma.rn.f32x2 %0, %1, %2, %3;" : "=l"(d) : "l"(a), "l"(b), "l"(c))
#define PACK_DUP_F32X2(out, v) \
    asm("mov.b64 %0, {%1, %1};" : "=l"(out) : "r"(__float_as_uint(v)))

// ---------------- 1) normalize rows (numerics FROZEN from R11) --------------
__global__ void normalize_kernel(const float* __restrict__ anchor,
                                 const float* __restrict__ pos,
                                 const float* __restrict__ neg,
                                 int B, int Nn) {
    int r = blockIdx.x * blockDim.x + threadIdx.x;
    int total = 2 * B + Nn;
    if (r >= total) return;

    const float* src;
    float* dst;
    if (r < B)            { src = anchor + (size_t)r * BD;         dst = g_an + (size_t)r * BD; }
    else if (r < 2 * B)   { src = pos    + (size_t)(r - B) * BD;   dst = g_cn + (size_t)(r - B) * BD; }
    else                  { src = neg    + (size_t)(r - 2*B) * BD; dst = g_cn + (size_t)(r - B) * BD; }

    float x[BD];
    #pragma unroll
    for (int k = 0; k < BD; ++k) x[k] = __ldg(src + k);

    float acc0[4] = {0.f, 0.f, 0.f, 0.f};
    float acc1[4] = {0.f, 0.f, 0.f, 0.f};
    #pragma unroll
    for (int i = 0; i < 8; ++i) {
        #pragma unroll
        for (int l = 0; l < 4; ++l)
            acc0[l] = __fadd_rn(acc0[l], __fmul_rn(x[8*i + l],     x[8*i + l]));     // UNFUSED
        #pragma unroll
        for (int l = 0; l < 4; ++l)
            acc1[l] = __fadd_rn(acc1[l], __fmul_rn(x[8*i + 4 + l], x[8*i + 4 + l])); // UNFUSED
    }
    float t0 = __fadd_rn(acc0[0], acc1[0]);
    float t1 = __fadd_rn(acc0[1], acc1[1]);
    float t2 = __fadd_rn(acc0[2], acc1[2]);
    float t3 = __fadd_rn(acc0[3], acc1[3]);
    float s  = __fadd_rn(__fadd_rn(t0, t1), __fadd_rn(t2, t3));   // faddp ladder

    float den = fmaxf(__fsqrt_rn(s), 1e-8f);
    float rcp = __fdiv_rn(1.0f, den);
    #pragma unroll
    for (int k = 0; k < BD; ++k)
        dst[k] = __fmul_rn(x[k], rcp);
}

// ---------------- 1b) diagonal + threshold init ------------------------------
// d_i = dot(an[i], cn[i]) via the EXACT per-thread chain the GEMM uses
// (k-ascending, single accumulator, fused) -> bit-identical to logits[i][i].
__global__ void diag_kernel(int B) {
    int r = blockIdx.x * blockDim.x + threadIdx.x;
    if (r >= B) return;
    const float* a = g_an + (size_t)r * BD;
    const float* c = g_cn + (size_t)r * BD;
    float s = 0.f;
    #pragma unroll
    for (int k = 0; k < BD; ++k)
        s = __fmaf_rn(a[k], c[k], s);
    g_diag[r]   = s;
    g_thresh[r] = fkey(CUDART_INF_F);   // +inf
}

// ---------------- 2) GEMM (FFMA2) + threshold epilogue ----------------------
// 128x128 tile, K=64, 8x8/thread. Accumulators packed in f32x2 pairs along j;
// each 32-bit half is the identical k-ascending fused chain (bit-exact).
// Epilogue: per-row masked max over this tile (or -inf), atomicMin -> g_thresh.
__global__ __launch_bounds__(256) void gemm_kernel(int M) {
    extern __shared__ float sm[];
    float* As = sm;                 // [64][TS] transposed: As[k*TS + m]
    float* Bs = sm + 64 * TS;       // [64][TS] transposed: Bs[k*TS + n]

    int t = threadIdx.x;            // 256 threads
    int rowBase = blockIdx.y * 128;
    int colBase = blockIdx.x * 128;

    {
        const float4* A4 = reinterpret_cast<const float4*>(g_an + (size_t)rowBase * BD);
        const float4* B4 = reinterpret_cast<const float4*>(g_cn + (size_t)colBase * BD);
        #pragma unroll
        for (int it = 0; it < 8; ++it) {
            int lin = it * 256 + t;
            int r   = lin >> 4;
            int kq  = lin & 15;
            float4 va = A4[r * 16 + kq];
            float4 vb = B4[r * 16 + kq];
            int k = kq * 4;
            As[(k+0)*TS + r] = va.x; As[(k+1)*TS + r] = va.y;
            As[(k+2)*TS + r] = va.z; As[(k+3)*TS + r] = va.w;
            Bs[(k+0)*TS + r] = vb.x; Bs[(k+1)*TS + r] = vb.y;
            Bs[(k+2)*TS + r] = vb.z; Bs[(k+3)*TS + r] = vb.w;
        }
    }
    __syncthreads();

    int tx = t & 15, ty = t >> 4;
    int r0 = ty * 8, c0 = tx * 8;

    unsigned long long accp[8][4];   // 8 rows x 4 column-pairs, f32x2 packed
    #pragma unroll
    for (int i = 0; i < 8; ++i)
        #pragma unroll
        for (int j = 0; j < 4; ++j)
            accp[i][j] = 0ull;       // two +0.0f halves

    #pragma unroll 8
    for (int k = 0; k < 64; ++k) {
        float4 a0 = *reinterpret_cast<const float4*>(&As[k*TS + r0]);
        float4 a1 = *reinterpret_cast<const float4*>(&As[k*TS + r0 + 4]);
        ulonglong2 bp0 = *reinterpret_cast<const ulonglong2*>(&Bs[k*TS + c0]);
        ulonglong2 bp1 = *reinterpret_cast<const ulonglong2*>(&Bs[k*TS + c0 + 4]);
        float a[8] = {a0.x,a0.y,a0.z,a0.w,a1.x,a1.y,a1.z,a1.w};
        unsigned long long bp[4] = {bp0.x, bp0.y, bp1.x, bp1.y};
        #pragma unroll
        for (int i = 0; i < 8; ++i) {
            unsigned long long aa;
            PACK_DUP_F32X2(aa, a[i]);
            #pragma unroll
            for (int j = 0; j < 4; ++j)
                FMA_F32X2(accp[i][j], aa, bp[j], accp[i][j]);   // fused, k-ascending per half
        }
    }

    // store logits + per-row masked max over this 8-col span
    #pragma unroll
    for (int i = 0; i < 8; ++i) {
        int row = rowBase + r0 + i;
        float* Cp = g_logits + (size_t)row * M + colBase + c0;
        reinterpret_cast<ulonglong2*>(Cp)[0] = make_ulonglong2(accp[i][0], accp[i][1]);
        reinterpret_cast<ulonglong2*>(Cp)[1] = make_ulonglong2(accp[i][2], accp[i][3]);

        float d = g_diag[row];
        float m = -CUDART_INF_F;
        #pragma unroll
        for (int j = 0; j < 4; ++j) {
            float2 p = *reinterpret_cast<float2*>(&accp[i][j]);
            if (p.x < d) m = fmaxf(m, p.x);
            if (p.y < d) m = fmaxf(m, p.y);
        }
        // reduce max over the 16 threads (same ty) owning this row
        #pragma unroll
        for (int off = 8; off; off >>= 1)
            m = fmaxf(m, __shfl_xor_sync(0xffffffffu, m, off));
        // ALWAYS contribute (possibly -inf): preserves the T=-inf safety property
        if (tx == 0) atomicMin(&g_thresh[row], fkey(m));
    }
}

// ---------------- 3) exact per-row top-32, SINGLE pass (warp per row) ------
// T precomputed by the GEMM epilogue. Guarantee: if all 128 tiles had masked
// values, >=128 masked >= T (superset of top-32); else T=-inf (all survive).
__global__ void topk_kernel(int B, int M) {
    int w    = (blockIdx.x * blockDim.x + threadIdx.x) >> 5;
    int lane = threadIdx.x & 31;
    if (w >= B) return;

    const float* __restrict__ Lrow = g_logits + (size_t)w * M;
    float d = Lrow[w];
    float T = funkey(g_thresh[w]);
    int iters = M >> 5;

    float lv[32]; int li[32];
    #pragma unroll
    for (int k = 0; k < 32; ++k) { lv[k] = -CUDART_INF_F; li[k] = 0x7FFFFFFF; }
    float curmin = -CUDART_INF_F; int minslot = 0;

    for (int i = 0; i < iters; ++i) {
        int   j = i * 32 + lane;
        float v = Lrow[j];
        if (v < d && v >= T && v > curmin) {
            lv[minslot] = v; li[minslot] = j;
            float mv = lv[0]; int mi = li[0]; int ms = 0;
            #pragma unroll
            for (int k = 1; k < 32; ++k) {
                if (lv[k] < mv || (lv[k] == mv && li[k] > mi)) { mv = lv[k]; mi = li[k]; ms = k; }
            }
            curmin = mv; minslot = ms;
        }
    }

    // merge: 32 exact warp-argmax iterations (value desc, index asc tie-break)
    float bv = lv[0]; int bi = li[0]; int bslot = 0;
    #pragma unroll
    for (int k = 1; k < 32; ++k)
        if (lv[k] > bv || (lv[k] == bv && li[k] < bi)) { bv = lv[k]; bi = li[k]; bslot = k; }

    for (int it = 0; it < 32; ++it) {
        float v = bv; int idx = bi;
        #pragma unroll
        for (int off = 16; off; off >>= 1) {
            float ov = __shfl_xor_sync(0xffffffffu, v,   off);
            int   oi = __shfl_xor_sync(0xffffffffu, idx, off);
            if (ov > v || (ov == v && oi < idx)) { v = ov; idx = oi; }
        }
        if (lane == 0) {
            bool valid = (idx != 0x7FFFFFFF);
            g_topi[w * 32 + it] = valid ? idx : -1;
            g_topv[w * 32 + it] = valid ? v : 0.f;
        }
        if (idx == bi && idx != 0x7FFFFFFF) {
            lv[bslot] = -CUDART_INF_F; li[bslot] = 0x7FFFFFFF;
            bv = lv[0]; bi = li[0]; bslot = 0;
            #pragma unroll
            for (int k = 1; k < 32; ++k)
                if (lv[k] > bv || (lv[k] == bv && li[k] < bi)) { bv = lv[k]; bi = li[k]; bslot = k; }
        }
    }
}

// ---------------- 4) zero-fill output, 5) scatter mined entries ------------
__global__ void fill_kernel(float4* __restrict__ out, size_t n4) {
    size_t i = (size_t)blockIdx.x * blockDim.x + threadIdx.x;
    if (i < n4) out[i] = make_float4(0.f, 0.f, 0.f, 0.f);
}

__global__ void scatter_kernel(float* __restrict__ out, int B, int M) {
    int idx = blockIdx.x * blockDim.x + threadIdx.x;
    if (idx >= B * 32) return;
    int row = idx >> 5;
    int j   = g_topi[idx];
    if (j >= 0) out[(size_t)row * M + j] = g_topv[idx];
}

// ---------------- launcher ---------------------------------------------------
extern "C" void kernel_launch(void* const* d_in, const int* in_sizes, int n_in,
                              void* d_out, int out_size) {
    const float* anchor = (const float*)d_in[0];
    const float* pos    = (const float*)d_in[1];
    const float* neg    = (const float*)d_in[2];
    float* out = (float*)d_out;

    int B  = in_sizes[0] / BD;   // 8192
    int Nn = in_sizes[2] / BD;   // 8192
    int M  = B + Nn;             // 16384

    // 1) normalize (numerics frozen)
    int totalRows = 2 * B + Nn;
    normalize_kernel<<<(totalRows + 127) / 128, 128>>>(anchor, pos, neg, B, Nn);

    // 1b) diagonal + threshold init
    diag_kernel<<<(B + 127) / 128, 128>>>(B);

    // 2) GEMM (FFMA2) + threshold epilogue -> g_logits, g_thresh
    int smemBytes = 2 * 64 * TS * (int)sizeof(float);   // 67584
    cudaFuncSetAttribute(gemm_kernel, cudaFuncAttributeMaxDynamicSharedMemorySize, smemBytes);
    dim3 ggrid(M / 128, B / 128);
    gemm_kernel<<<ggrid, 256, smemBytes>>>(M);

    // 3) exact top-32 per row, single pass
    topk_kernel<<<(B * 32 + 255) / 256, 256>>>(B, M);

    // 4) zero-fill output
    size_t n4 = ((size_t)B * M) / 4;
    fill_kernel<<<(unsigned)((n4 + 255) / 256), 256>>>((float4*)out, n4);

    // 5) scatter mined (value, index) pairs
    scatter_kernel<<<(B * 32 + 255) / 256, 256>>>(out, B, M);
}